// round 6
// baseline (speedup 1.0000x reference)
#include <cuda_runtime.h>
#include <cmath>

// ive(v=49.5, z) = ex2( 49.5*lg2(z) - z/ln2 - lgamma(50.5)/ln2 - 49.5 + lnS(z^2)/ln2 )
// with S(s) = sum_k (s/4)^k / (k! (v+1)_k).
//
// lnS(s)/ln2 on s in [0.25, 9900.25]: degree-14 Chebyshev fit (nearest singularity
// s ~ -3203 -> rho ~ 2.94), monomial Horner in t=(s-s0)/h, packed fma.rn.f32x2.
//
// Round-6: kernel is memory-latency/issue bound (R3/R4/R5 all ~48.9us despite
// -30% compute). Changes: EPT=8 with TWO front-batched LDG.128 (per-warp MLP=2),
// 4 packed Horner chains per LDS.64 coefficient broadcast (halves per-element
// overhead), NP 16->14. Single ex2 finish with +64 bias / 2^-64 non-FTZ descale
// keeps denormal outputs correctly rounded (validated R5: rel_err 1.9e-5).

#define NP  14
#define TPB 256
#define EPT 8

struct QTab { float q[NP + 1]; float c64; };

static QTab make_tab_host() {
    const double VD = 49.5, S0 = 4950.25, HH = 4950.0;
    const double LN2 = 0.69314718055994530942;
    const int M = 64;
    double f[M];
    for (int j = 0; j < M; j++) {
        double x = std::cos(M_PI * (j + 0.5) / M);
        double s = S0 + HH * x;
        double T = 1.0, sum = 1.0;
        for (int k = 1; k < 700; k++) {
            T *= s / (4.0 * (double)k * (VD + (double)k));
            sum += T;
            if (k > 40 && T < sum * 1e-19) break;
        }
        f[j] = std::log(sum) / LN2;
    }
    double c[NP + 1];
    for (int k = 0; k <= NP; k++) {
        double acc = 0.0;
        for (int j = 0; j < M; j++) acc += f[j] * std::cos(M_PI * k * (j + 0.5) / M);
        c[k] = 2.0 * acc / M;
    }
    c[0] *= 0.5;
    double a[NP + 1] = {0}, Tp[NP + 1] = {0}, Tc[NP + 1] = {0}, Tn[NP + 1];
    Tp[0] = 1.0; a[0] += c[0];
    Tc[1] = 1.0; a[1] += c[1];
    for (int k = 2; k <= NP; k++) {
        for (int m = 0; m <= NP; m++) {
            double v = -Tp[m];
            if (m > 0) v += 2.0 * Tc[m - 1];
            Tn[m] = v;
        }
        for (int m = 0; m <= k; m++) a[m] += c[k] * Tn[m];
        for (int m = 0; m <= NP; m++) { Tp[m] = Tc[m]; Tc[m] = Tn[m]; }
    }
    QTab t;
    for (int m = 0; m <= NP; m++) t.q[m] = (float)a[m];
    t.c64 = (float)(-(std::lgamma(50.5) / LN2) - 49.5 + 64.0);
    return t;
}
static const QTab H_Q = make_tab_host();   // host static init only

typedef unsigned long long ull;
__device__ __forceinline__ ull pack2(float a, float b) {
    ull r; asm("mov.b64 %0, {%1, %2};" : "=l"(r) : "f"(a), "f"(b)); return r;
}
__device__ __forceinline__ void unpack2(ull v, float& a, float& b) {
    asm("mov.b64 {%0, %1}, %2;" : "=f"(a), "=f"(b) : "l"(v));
}
__device__ __forceinline__ ull fma2(ull a, ull b, ull c) {
    ull d; asm("fma.rn.f32x2 %0, %1, %2, %3;" : "=l"(d) : "l"(a), "l"(b), "l"(c));
    return d;
}
__device__ __forceinline__ ull mul2(ull a, ull b) {
    ull d; asm("mul.rn.f32x2 %0, %1, %2;" : "=l"(d) : "l"(a), "l"(b)); return d;
}
__device__ __forceinline__ ull add2(ull a, ull b) {
    ull d; asm("add.rn.f32x2 %0, %1, %2;" : "=l"(d) : "l"(a), "l"(b)); return d;
}
__device__ __forceinline__ float lg2f(float x) {
    float r; asm("lg2.approx.f32 %0, %1;" : "=f"(r) : "f"(x)); return r;
}
__device__ __forceinline__ float ex2f(float x) {
    float r; asm("ex2.approx.f32 %0, %1;" : "=f"(r) : "f"(x)); return r;
}
__device__ __forceinline__ float mulrn(float a, float b) {   // non-FTZ multiply
    float r; asm("mul.rn.f32 %0, %1, %2;" : "=f"(r) : "f"(a), "f"(b)); return r;
}

// out = ex2( 49.5*lg2(z) + g ) * 2^-64,  g = -z/ln2 + c64 + lnS/ln2 (precombined)
__device__ __forceinline__ float finish(float z, float g) {
    return mulrn(ex2f(fmaf(49.5f, lg2f(z), g)), 5.421010862427522e-20f);
}

__global__ void __launch_bounds__(TPB)
ive_kernel(const float* __restrict__ zin, float* __restrict__ out, int n, QTab tab) {
    __shared__ float2 qs[NP + 1];
    if (threadIdx.x <= NP) {
        float v = tab.q[threadIdx.x];
        qs[threadIdx.x] = make_float2(v, v);
    }
    __syncthreads();

    const float HIF = 1.0f / 4950.0f;
    const float HCF = -4950.25f / 4950.0f;
    const ull HI2  = pack2(HIF, HIF);
    const ull HC2  = pack2(HCF, HCF);
    const ull NIL2 = pack2(-1.44269504088896341f, -1.44269504088896341f);
    const ull C642 = pack2(tab.c64, tab.c64);

    int base = (blockIdx.x * TPB + threadIdx.x) * EPT;
    if (base + EPT <= n) {
        // two front-batched 128-bit loads -> per-warp MLP = 2
        float4 a = __ldcs((const float4*)(zin + base));
        float4 b = __ldcs((const float4*)(zin + base + 4));
        ull Z[4] = {pack2(a.x, a.y), pack2(a.z, a.w),
                    pack2(b.x, b.y), pack2(b.z, b.w)};
        ull T[4], R[4];
        {
            float2 qt = qs[NP];
            ull Qt = pack2(qt.x, qt.y);
#pragma unroll
            for (int i = 0; i < 4; i++) {
                T[i] = fma2(mul2(Z[i], Z[i]), HI2, HC2);   // t = (z*z - s0)/h
                R[i] = Qt;
            }
        }
#pragma unroll
        for (int m = NP - 1; m >= 0; m--) {
            float2 qm = qs[m];
            ull Qm = pack2(qm.x, qm.y);                    // one LDS.64 feeds 4 chains
            R[0] = fma2(R[0], T[0], Qm);
            R[1] = fma2(R[1], T[1], Qm);
            R[2] = fma2(R[2], T[2], Qm);
            R[3] = fma2(R[3], T[3], Qm);
        }
        float zz[8] = {a.x, a.y, a.z, a.w, b.x, b.y, b.z, b.w};
        float r[8];
#pragma unroll
        for (int i = 0; i < 4; i++) {
            ull G = add2(fma2(Z[i], NIL2, C642), R[i]);    // g = -z/ln2 + c64 + P(t)
            float g0, g1;
            unpack2(G, g0, g1);
            r[2 * i]     = finish(zz[2 * i],     g0);
            r[2 * i + 1] = finish(zz[2 * i + 1], g1);
        }
        __stcs((float4*)(out + base),     make_float4(r[0], r[1], r[2], r[3]));
        __stcs((float4*)(out + base + 4), make_float4(r[4], r[5], r[6], r[7]));
    } else {
        int end = (n < base + EPT) ? n : base + EPT;
        for (int i = base; i < end; i++) {
            float z = zin[i];
            float t = fmaf(z * z, HIF, HCF);
            float rr = tab.q[NP];
            for (int m = NP - 1; m >= 0; m--) rr = fmaf(rr, t, tab.q[m]);
            float g = fmaf(z, -1.44269504088896341f, tab.c64) + rr;
            out[i] = finish(z, g);
        }
    }
}

extern "C" void kernel_launch(void* const* d_in, const int* in_sizes, int n_in,
                              void* d_out, int out_size) {
    const float* z = (const float*)d_in[0];
    float* o = (float*)d_out;
    int n = in_sizes[0];
    if (n <= 0) return;
    int per_block = TPB * EPT;
    int grid = (n + per_block - 1) / per_block;
    ive_kernel<<<grid, TPB>>>(z, o, n, H_Q);
}

// round 7
// speedup vs baseline: 1.3004x; 1.3004x over previous
#include <cuda_runtime.h>
#include <cmath>

// ive(v=49.5, z) = ex2( 49.5*lg2(z) - z/ln2 - lgamma(50.5)/ln2 - 49.5 + lnS(z^2)/ln2 )
// with S(s) = sum_k (s/4)^k / (k! (v+1)_k).
//
// lnS(s)/ln2 on s in [0.25, 9900.25]: degree-14 Chebyshev fit (nearest singularity
// s ~ -3203 -> rho ~ 2.94; fit err validated in R6 at rel_err 1.9e-5), monomial
// Horner in t=(s-s0)/h with packed fma.rn.f32x2 (2 elems/instr).
//
// R7: revert of R6's EPT=8 (its zz[8] scalar array spilled to local memory ->
// 67us). Back to EPT=4 all-packed-register structure (R5, 48.9us) with:
//  - NP 14 (2 fewer FFMA2 rounds)
//  - lg2(z) MUFU calls hoisted BEFORE the Horner so their 16-cyc latency hides
//    under the fma chain instead of serializing in the tail.
// Single ex2 finish, +64 exponent bias, 2^-64 non-FTZ descale for correct
// denormal rounding (matches reference exp underflow path).

#define NP  14
#define TPB 256
#define EPT 4

struct QTab { float q[NP + 1]; float c64; };

static QTab make_tab_host() {
    const double VD = 49.5, S0 = 4950.25, HH = 4950.0;
    const double LN2 = 0.69314718055994530942;
    const int M = 64;
    double f[M];
    for (int j = 0; j < M; j++) {
        double x = std::cos(M_PI * (j + 0.5) / M);
        double s = S0 + HH * x;
        double T = 1.0, sum = 1.0;
        for (int k = 1; k < 700; k++) {
            T *= s / (4.0 * (double)k * (VD + (double)k));
            sum += T;
            if (k > 40 && T < sum * 1e-19) break;
        }
        f[j] = std::log(sum) / LN2;
    }
    double c[NP + 1];
    for (int k = 0; k <= NP; k++) {
        double acc = 0.0;
        for (int j = 0; j < M; j++) acc += f[j] * std::cos(M_PI * k * (j + 0.5) / M);
        c[k] = 2.0 * acc / M;
    }
    c[0] *= 0.5;
    double a[NP + 1] = {0}, Tp[NP + 1] = {0}, Tc[NP + 1] = {0}, Tn[NP + 1];
    Tp[0] = 1.0; a[0] += c[0];
    Tc[1] = 1.0; a[1] += c[1];
    for (int k = 2; k <= NP; k++) {
        for (int m = 0; m <= NP; m++) {
            double v = -Tp[m];
            if (m > 0) v += 2.0 * Tc[m - 1];
            Tn[m] = v;
        }
        for (int m = 0; m <= k; m++) a[m] += c[k] * Tn[m];
        for (int m = 0; m <= NP; m++) { Tp[m] = Tc[m]; Tc[m] = Tn[m]; }
    }
    QTab t;
    for (int m = 0; m <= NP; m++) t.q[m] = (float)a[m];
    t.c64 = (float)(-(std::lgamma(50.5) / LN2) - 49.5 + 64.0);
    return t;
}
static const QTab H_Q = make_tab_host();   // host static init only

typedef unsigned long long ull;
__device__ __forceinline__ ull pack2(float a, float b) {
    ull r; asm("mov.b64 %0, {%1, %2};" : "=l"(r) : "f"(a), "f"(b)); return r;
}
__device__ __forceinline__ void unpack2(ull v, float& a, float& b) {
    asm("mov.b64 {%0, %1}, %2;" : "=f"(a), "=f"(b) : "l"(v));
}
__device__ __forceinline__ ull fma2(ull a, ull b, ull c) {
    ull d; asm("fma.rn.f32x2 %0, %1, %2, %3;" : "=l"(d) : "l"(a), "l"(b), "l"(c));
    return d;
}
__device__ __forceinline__ ull mul2(ull a, ull b) {
    ull d; asm("mul.rn.f32x2 %0, %1, %2;" : "=l"(d) : "l"(a), "l"(b)); return d;
}
__device__ __forceinline__ ull add2(ull a, ull b) {
    ull d; asm("add.rn.f32x2 %0, %1, %2;" : "=l"(d) : "l"(a), "l"(b)); return d;
}
__device__ __forceinline__ float lg2f(float x) {
    float r; asm("lg2.approx.f32 %0, %1;" : "=f"(r) : "f"(x)); return r;
}
__device__ __forceinline__ float ex2f(float x) {
    float r; asm("ex2.approx.f32 %0, %1;" : "=f"(r) : "f"(x)); return r;
}
__device__ __forceinline__ float mulrn(float a, float b) {   // non-FTZ multiply
    float r; asm("mul.rn.f32 %0, %1, %2;" : "=f"(r) : "f"(a), "f"(b)); return r;
}

__global__ void __launch_bounds__(TPB)
ive_kernel(const float* __restrict__ zin, float* __restrict__ out, int n, QTab tab) {
    __shared__ float2 qs[NP + 1];
    if (threadIdx.x <= NP) {
        float v = tab.q[threadIdx.x];
        qs[threadIdx.x] = make_float2(v, v);
    }
    __syncthreads();

    const float HIF = 1.0f / 4950.0f;
    const float HCF = -4950.25f / 4950.0f;
    const ull HI2  = pack2(HIF, HIF);
    const ull HC2  = pack2(HCF, HCF);
    const ull NIL2 = pack2(-1.44269504088896341f, -1.44269504088896341f);
    const ull C642 = pack2(tab.c64, tab.c64);

    int base = (blockIdx.x * TPB + threadIdx.x) * EPT;
    if (base + EPT <= n) {
        float4 a = __ldcs((const float4*)(zin + base));
        ull Z0 = pack2(a.x, a.y), Z1 = pack2(a.z, a.w);

        // MUFU lg2 issued EARLY: 16-cyc latency hides under the Horner chain.
        float l0 = lg2f(a.x), l1 = lg2f(a.y), l2 = lg2f(a.z), l3 = lg2f(a.w);

        ull T0 = fma2(mul2(Z0, Z0), HI2, HC2);          // t = (z*z - s0)/h
        ull T1 = fma2(mul2(Z1, Z1), HI2, HC2);
        ull E0 = fma2(Z0, NIL2, C642);                  // -z/ln2 + c64
        ull E1 = fma2(Z1, NIL2, C642);

        float2 qt = qs[NP];
        ull R0 = pack2(qt.x, qt.y), R1 = R0;
#pragma unroll
        for (int m = NP - 1; m >= 0; m--) {
            float2 qm = qs[m];
            ull Qm = pack2(qm.x, qm.y);                 // LDS.64 broadcast
            R0 = fma2(R0, T0, Qm);
            R1 = fma2(R1, T1, Qm);
        }
        ull G0 = add2(E0, R0);                          // g = -z/ln2 + c64 + P(t)
        ull G1 = add2(E1, R1);

        float g0, g1, g2, g3;
        unpack2(G0, g0, g1); unpack2(G1, g2, g3);
        const float DS = 5.421010862427522e-20f;        // 2^-64
        float4 r = make_float4(
            mulrn(ex2f(fmaf(49.5f, l0, g0)), DS),
            mulrn(ex2f(fmaf(49.5f, l1, g1)), DS),
            mulrn(ex2f(fmaf(49.5f, l2, g2)), DS),
            mulrn(ex2f(fmaf(49.5f, l3, g3)), DS));
        __stcs((float4*)(out + base), r);
    } else {
        int end = (n < base + EPT) ? n : base + EPT;
        for (int i = base; i < end; i++) {
            float z = zin[i];
            float t = fmaf(z * z, HIF, HCF);
            float rr = tab.q[NP];
            for (int m = NP - 1; m >= 0; m--) rr = fmaf(rr, t, tab.q[m]);
            float g = fmaf(z, -1.44269504088896341f, tab.c64) + rr;
            out[i] = mulrn(ex2f(fmaf(49.5f, lg2f(z), g)), 5.421010862427522e-20f);
        }
    }
}

extern "C" void kernel_launch(void* const* d_in, const int* in_sizes, int n_in,
                              void* d_out, int out_size) {
    const float* z = (const float*)d_in[0];
    float* o = (float*)d_out;
    int n = in_sizes[0];
    if (n <= 0) return;
    int per_block = TPB * EPT;
    int grid = (n + per_block - 1) / per_block;
    ive_kernel<<<grid, TPB>>>(z, o, n, H_Q);
}